// round 2
// baseline (speedup 1.0000x reference)
#include <cuda_runtime.h>
#include <cuda_bf16.h>
#include <math.h>

// Problem dims (fixed by the reference)
#define NSEQ 8192
#define CDIM 1024
#define HDIM 128

// ---------------------------------------------------------------------------
// Scratch: __device__ globals (no cudaMalloc allowed anywhere)
// ---------------------------------------------------------------------------
__device__ __align__(256) float g_q [NSEQ * HDIM];            //  4 MB
__device__ __align__(256) float g_k [NSEQ * HDIM];            //  4 MB
__device__ __align__(256) float g_v [NSEQ * CDIM];            // 32 MB
__device__ __align__(256) float g_s [(size_t)NSEQ * NSEQ];    // 256 MB
__device__ __align__(256) float g_av[NSEQ * CDIM];            // 32 MB

// ---------------------------------------------------------------------------
// Tiled SGEMM. TRANS_B=true : C[M,Nc] = alpha * A[M,K] @ B[Nc,K]^T (+bias)
//              TRANS_B=false: C[M,Nc] = alpha * A[M,K] @ B[K,Nc]   (+bias)
// BM=BN=128, BK=16, 8x8 per thread, 256 threads. All dims divide tiles.
// ---------------------------------------------------------------------------
template <bool TRANS_B, bool HAS_BIAS>
__global__ void __launch_bounds__(256)
gemm_kernel(const float* __restrict__ A, const float* __restrict__ B,
            const float* __restrict__ bias, float* __restrict__ C,
            int M, int Nc, int K, float alpha)
{
    constexpr int BM = 128, BN = 128, BK = 16, TM = 8, TN = 8;
    __shared__ float As[BK][BM];
    __shared__ float Bs[BK][BN];

    const int tid = threadIdx.x;
    const int tx  = tid & 15;   // 0..15 (col thread)
    const int ty  = tid >> 4;   // 0..15 (row thread)
    const int rowBase = blockIdx.y * BM;
    const int colBase = blockIdx.x * BN;

    float acc[TM][TN] = {};

    for (int k0 = 0; k0 < K; k0 += BK) {
        // ---- load A tile (BM x BK) transposed into As[k][m] ----
        #pragma unroll
        for (int i = 0; i < 2; i++) {
            int f  = tid + i * 256;        // 0..511 float4 slots
            int r  = f >> 2;               // 0..127
            int cg = f & 3;                // 0..3 (float4 group in BK)
            float4 va = *reinterpret_cast<const float4*>(
                &A[(size_t)(rowBase + r) * K + k0 + cg * 4]);
            As[cg * 4 + 0][r] = va.x;
            As[cg * 4 + 1][r] = va.y;
            As[cg * 4 + 2][r] = va.z;
            As[cg * 4 + 3][r] = va.w;
        }
        // ---- load B tile into Bs[k][n] ----
        if (TRANS_B) {
            #pragma unroll
            for (int i = 0; i < 2; i++) {
                int f  = tid + i * 256;
                int r  = f >> 2;           // n within tile, 0..127
                int cg = f & 3;
                float4 vb = *reinterpret_cast<const float4*>(
                    &B[(size_t)(colBase + r) * K + k0 + cg * 4]);
                Bs[cg * 4 + 0][r] = vb.x;
                Bs[cg * 4 + 1][r] = vb.y;
                Bs[cg * 4 + 2][r] = vb.z;
                Bs[cg * 4 + 3][r] = vb.w;
            }
        } else {
            #pragma unroll
            for (int i = 0; i < 2; i++) {
                int f  = tid + i * 256;    // 0..511
                int r  = f >> 5;           // k row 0..15 (32 float4 per row)
                int cg = f & 31;
                float4 vb = *reinterpret_cast<const float4*>(
                    &B[(size_t)(k0 + r) * Nc + colBase + cg * 4]);
                *reinterpret_cast<float4*>(&Bs[r][cg * 4]) = vb;
            }
        }
        __syncthreads();

        // ---- compute ----
        #pragma unroll
        for (int kk = 0; kk < BK; kk++) {
            float ra[TM], rb[TN];
            #pragma unroll
            for (int i = 0; i < TM; i++) ra[i] = As[kk][ty * TM + i];
            #pragma unroll
            for (int j = 0; j < TN; j++) rb[j] = Bs[kk][tx * TN + j];
            #pragma unroll
            for (int i = 0; i < TM; i++)
                #pragma unroll
                for (int j = 0; j < TN; j++)
                    acc[i][j] += ra[i] * rb[j];
        }
        __syncthreads();
    }

    // ---- epilogue ----
    #pragma unroll
    for (int i = 0; i < TM; i++) {
        int r = rowBase + ty * TM + i;
        #pragma unroll
        for (int j = 0; j < TN; j += 4) {
            int c = colBase + tx * TN + j;
            float4 o;
            o.x = alpha * acc[i][j + 0];
            o.y = alpha * acc[i][j + 1];
            o.z = alpha * acc[i][j + 2];
            o.w = alpha * acc[i][j + 3];
            if (HAS_BIAS) {
                o.x += bias[c + 0];
                o.y += bias[c + 1];
                o.z += bias[c + 2];
                o.w += bias[c + 3];
            }
            *reinterpret_cast<float4*>(&C[(size_t)r * Nc + c]) = o;
        }
    }
}

// ---------------------------------------------------------------------------
// Row softmax over NSEQ floats, in place. One block (256 threads) per row;
// 32 elements/thread held in registers, two block reductions (max, sum).
// ---------------------------------------------------------------------------
__global__ void __launch_bounds__(256)
softmax_kernel(float* __restrict__ S)
{
    const int row = blockIdx.x;
    float4* p = reinterpret_cast<float4*>(S + (size_t)row * NSEQ);
    const int tid = threadIdx.x;

    float4 v[8];
    float mx = -INFINITY;
    #pragma unroll
    for (int i = 0; i < 8; i++) {
        v[i] = p[tid + i * 256];
        mx = fmaxf(mx, fmaxf(fmaxf(v[i].x, v[i].y), fmaxf(v[i].z, v[i].w)));
    }

    __shared__ float red[8];
    __shared__ float bcast;
    const int lane = tid & 31, warp = tid >> 5;

    // block max
    #pragma unroll
    for (int o = 16; o > 0; o >>= 1) mx = fmaxf(mx, __shfl_xor_sync(~0u, mx, o));
    if (lane == 0) red[warp] = mx;
    __syncthreads();
    if (warp == 0) {
        float m = (lane < 8) ? red[lane] : -INFINITY;
        #pragma unroll
        for (int o = 4; o > 0; o >>= 1) m = fmaxf(m, __shfl_xor_sync(~0u, m, o));
        if (lane == 0) bcast = m;
    }
    __syncthreads();
    mx = bcast;
    __syncthreads();

    // exp + sum
    float sum = 0.f;
    #pragma unroll
    for (int i = 0; i < 8; i++) {
        v[i].x = expf(v[i].x - mx);
        v[i].y = expf(v[i].y - mx);
        v[i].z = expf(v[i].z - mx);
        v[i].w = expf(v[i].w - mx);
        sum += v[i].x + v[i].y + v[i].z + v[i].w;
    }
    #pragma unroll
    for (int o = 16; o > 0; o >>= 1) sum += __shfl_xor_sync(~0u, sum, o);
    if (lane == 0) red[warp] = sum;
    __syncthreads();
    if (warp == 0) {
        float s = (lane < 8) ? red[lane] : 0.f;
        #pragma unroll
        for (int o = 4; o > 0; o >>= 1) s += __shfl_xor_sync(~0u, s, o);
        if (lane == 0) bcast = s;
    }
    __syncthreads();
    const float inv = 1.f / bcast;

    #pragma unroll
    for (int i = 0; i < 8; i++) {
        v[i].x *= inv; v[i].y *= inv; v[i].z *= inv; v[i].w *= inv;
        p[tid + i * 256] = v[i];
    }
}

// ---------------------------------------------------------------------------
// Launch
// ---------------------------------------------------------------------------
extern "C" void kernel_launch(void* const* d_in, const int* in_sizes, int n_in,
                              void* d_out, int out_size)
{
    const float* x  = (const float*)d_in[0];
    const float* Wq = (const float*)d_in[1];
    const float* bq = (const float*)d_in[2];
    const float* Wk = (const float*)d_in[3];
    const float* bk = (const float*)d_in[4];
    const float* Wv = (const float*)d_in[5];
    const float* bv = (const float*)d_in[6];
    const float* Wo = (const float*)d_in[7];
    const float* bo = (const float*)d_in[8];
    float* out = (float*)d_out;

    float *q, *k, *v, *s, *av;
    cudaGetSymbolAddress((void**)&q,  g_q);
    cudaGetSymbolAddress((void**)&k,  g_k);
    cudaGetSymbolAddress((void**)&v,  g_v);
    cudaGetSymbolAddress((void**)&s,  g_s);
    cudaGetSymbolAddress((void**)&av, g_av);

    const float scale = 1.0f / sqrtf((float)HDIM);
    const dim3 blk(256);

    // q = x @ Wq^T + bq   (8192x128)
    gemm_kernel<true, true><<<dim3(HDIM / 128, NSEQ / 128), blk>>>(
        x, Wq, bq, q, NSEQ, HDIM, CDIM, 1.0f);
    // k = x @ Wk^T + bk
    gemm_kernel<true, true><<<dim3(HDIM / 128, NSEQ / 128), blk>>>(
        x, Wk, bk, k, NSEQ, HDIM, CDIM, 1.0f);
    // v = x @ Wv^T + bv   (8192x1024)
    gemm_kernel<true, true><<<dim3(CDIM / 128, NSEQ / 128), blk>>>(
        x, Wv, bv, v, NSEQ, CDIM, CDIM, 1.0f);
    // S = scale * q @ k^T (8192x8192)
    gemm_kernel<true, false><<<dim3(NSEQ / 128, NSEQ / 128), blk>>>(
        q, k, nullptr, s, NSEQ, NSEQ, HDIM, scale);
    // softmax rows in place
    softmax_kernel<<<NSEQ, blk>>>(s);
    // av = S @ v          (8192x1024) — B not transposed
    gemm_kernel<false, false><<<dim3(CDIM / 128, NSEQ / 128), blk>>>(
        s, v, nullptr, av, NSEQ, CDIM, NSEQ, 1.0f);
    // out = av @ Wo^T + bo
    gemm_kernel<true, true><<<dim3(CDIM / 128, NSEQ / 128), blk>>>(
        av, Wo, bo, out, NSEQ, CDIM, CDIM, 1.0f);
}